// round 2
// baseline (speedup 1.0000x reference)
#include <cuda_runtime.h>
#include <cfloat>

// Problem constants
constexpr int B_ = 32768;   // batch
constexpr int P_ = 4;       // slots
constexpr int C_ = 512;     // classes

// All 24 permutations of (0,1,2,3), packed 2 bits per slot:
// value = perm[0] | perm[1]<<2 | perm[2]<<4 | perm[3]<<6
__constant__ unsigned char c_perms[24] = {
    228, 180, 216, 120, 156, 108,   // 0123 0132 0213 0231 0312 0321
    225, 177, 201,  57, 141,  45,   // 1023 1032 1203 1230 1302 1320
    210, 114, 198,  54,  78,  30,   // 2013 2031 2103 2130 2301 2310
    147,  99, 135,  39,  75,  27    // 3012 3021 3102 3120 3201 3210
};

__global__ __launch_bounds__(256)
void pce_kernel(const float* __restrict__ preds,
                const int* __restrict__ targets,
                float* __restrict__ out)
{
    const unsigned FULL = 0xffffffffu;
    const int lane = threadIdx.x & 31;
    const int b    = blockIdx.x * (blockDim.x >> 5) + (threadIdx.x >> 5);
    if (b >= B_) return;

    const size_t base = (size_t)b * (P_ * C_);

    // Each of lanes 0..23 owns one permutation (packed byte).
    const unsigned myperm = c_perms[lane < 24 ? lane : 0];

    // Lanes 0..3 hold the 4 target classes for this batch (int32 per harness).
    int tc = 0;
    if (lane < 4) tc = targets[b * 4 + lane];

    float mysum = 0.f;  // per-lane permutation accumulator (lanes 0..23)

    #pragma unroll
    for (int p = 0; p < P_; p++) {
        const float4* row = (const float4*)(preds + base + p * C_);
        // 512 floats = 128 float4; lane strides by 32 -> fully coalesced LDG.128
        float4 v0 = row[lane];
        float4 v1 = row[lane + 32];
        float4 v2 = row[lane + 64];
        float4 v3 = row[lane + 96];

        // local max over 16 values
        float m = fmaxf(fmaxf(fmaxf(v0.x, v0.y), fmaxf(v0.z, v0.w)),
                 fmaxf(fmaxf(fmaxf(v1.x, v1.y), fmaxf(v1.z, v1.w)),
                 fmaxf(fmaxf(fmaxf(v2.x, v2.y), fmaxf(v2.z, v2.w)),
                       fmaxf(fmaxf(v3.x, v3.y), fmaxf(v3.z, v3.w)))));
        // warp max reduce
        #pragma unroll
        for (int off = 16; off >= 1; off >>= 1)
            m = fmaxf(m, __shfl_xor_sync(FULL, m, off));

        // local sum of exp(x - m)
        float s = __expf(v0.x - m) + __expf(v0.y - m) + __expf(v0.z - m) + __expf(v0.w - m)
                + __expf(v1.x - m) + __expf(v1.y - m) + __expf(v1.z - m) + __expf(v1.w - m)
                + __expf(v2.x - m) + __expf(v2.y - m) + __expf(v2.z - m) + __expf(v2.w - m)
                + __expf(v3.x - m) + __expf(v3.y - m) + __expf(v3.z - m) + __expf(v3.w - m);
        // warp sum reduce
        #pragma unroll
        for (int off = 16; off >= 1; off >>= 1)
            s += __shfl_xor_sync(FULL, s, off);

        const float lse = m + __logf(s);

        // Gather log-prob of the 4 target classes for this row (L1-hot: row
        // was just streamed by this warp), broadcast to all lanes.
        float g = 0.f;
        if (lane < 4) g = preds[base + p * C_ + tc] - lse;
        const float g0 = __shfl_sync(FULL, g, 0);
        const float g1 = __shfl_sync(FULL, g, 1);
        const float g2 = __shfl_sync(FULL, g, 2);
        const float g3 = __shfl_sync(FULL, g, 3);

        // lane k accumulates g[perm_k[p]]
        const int j = (myperm >> (2 * p)) & 3;
        const float gv = (j == 0) ? g0 : (j == 1) ? g1 : (j == 2) ? g2 : g3;
        mysum += gv;
    }

    // min over permutations of (-sum)  ==  -(max over permutations of sum)
    if (lane >= 24) mysum = -FLT_MAX;
    #pragma unroll
    for (int off = 16; off >= 1; off >>= 1)
        mysum = fmaxf(mysum, __shfl_xor_sync(FULL, mysum, off));

    if (lane == 0) out[b] = -mysum;
}

extern "C" void kernel_launch(void* const* d_in, const int* in_sizes, int n_in,
                              void* d_out, int out_size)
{
    const float* preds   = (const float*)d_in[0];
    const int*   targets = (const int*)d_in[1];
    float*       out     = (float*)d_out;

    // 8 warps/block, one warp per batch row
    const int threads = 256;
    const int warps_per_block = threads / 32;
    const int blocks = (B_ + warps_per_block - 1) / warps_per_block;  // 4096
    pce_kernel<<<blocks, threads>>>(preds, targets, out);
}